// round 7
// baseline (speedup 1.0000x reference)
#include <cuda_runtime.h>
#include <math.h>

// Problem constants
#define B 256
#define N 256
#define D 512
#define EPSV 1e-8f

#define DSPLIT 16
#define DCHUNK (D / DSPLIT)   // 32 d's per block
#define DC4 (DCHUNK / 4)      // 8 float4 columns per block
#define NGROUPS 32
#define NCHUNK (N / NGROUPS)  // 8 n-rows per thread
// block = DC4 * NGROUPS = 256 threads

#define D4 (D / 4)               // 128
#define PB4 ((N + D) * D4)       // new_pd float4 stride per batch = 98304
#define DIAG4 (N * D4)           // diag region offset within batch = 32768

// Register-cached mega-kernel, higher occupancy variant: block (b, h) owns a
// 32-d-chunk of batch b; each thread caches 8 float4 (32 regs) so 4 blocks
// fit per SM (occ ~47%), letting different blocks' phases interleave and keep
// the memory system saturated across the __syncthreads boundaries.
//  Pass 1: load slice into registers (abs-sum) + interleaved diag zero-fill.
//  Reduce: lam/beta/delta; write new_central/new_err; patch 32 diag scalars.
//  Pass 2: scale register-resident values, store scaled_pd.
//  pd read from DRAM exactly once.
__global__ __launch_bounds__(256, 4) void k_mega(const float* __restrict__ cv,
                                                 const float4* __restrict__ pd4,
                                                 const float* __restrict__ err,
                                                 float* __restrict__ out_central,
                                                 float4* __restrict__ out_pd4,
                                                 float* __restrict__ out_err) {
    const int b = blockIdx.x;
    const int h = blockIdx.y;        // d-chunk index, 0..15
    const int tid = threadIdx.x;
    const int d4 = tid & (DC4 - 1);  // 0..7  (float4 column within chunk)
    const int g = tid >> 3;          // 0..31 (n-group)

    __shared__ float4 s_acc[NGROUPS][DC4];
    __shared__ float4 s_lam[DC4];

    // Base pointer for this thread's float4 column of the pd slice
    const float4* p = pd4 + (size_t)b * N * D4 + (size_t)(g * NCHUNK) * D4
                      + h * DC4 + d4;

    // Diag share of this block: rows [h*32, h*32+32) of batch b
    // = 32 rows * 128 float4 = 4096 float4; zero-filled 512 float4/iter.
    float4* diag_blk = out_pd4 + (size_t)b * PB4 + DIAG4 + (size_t)h * DCHUNK * D4;
    const float4 z = make_float4(0.f, 0.f, 0.f, 0.f);

    // Pass 1: load slice into registers + abs-sum + diag zero-fill interleave
    float4 v[NCHUNK];
    float4 acc = make_float4(0.f, 0.f, 0.f, 0.f);
#pragma unroll
    for (int n = 0; n < NCHUNK; n++) {
        v[n] = p[(size_t)n * D4];
        diag_blk[n * 512 + tid] = z;
        diag_blk[n * 512 + 256 + tid] = z;
        acc.x += fabsf(v[n].x);
        acc.y += fabsf(v[n].y);
        acc.z += fabsf(v[n].z);
        acc.w += fabsf(v[n].w);
    }
    s_acc[g][d4] = acc;
    __syncthreads();

    // Combine groups + compute lam/beta/delta: threads 0..31, one d each
    if (tid < DCHUNK) {
        const int dc4 = tid >> 2;
        const int lane = tid & 3;
        float r = 0.f;
#pragma unroll
        for (int gg = 0; gg < NGROUPS; gg++)
            r += ((const float*)&s_acc[gg][dc4])[lane];

        const int dg = h * DCHUNK + tid;  // global d index
        const int bd = b * D + dg;
        const float e = err[bd];
        const float c = cv[bd];

        const float radius = r + fabsf(e);
        const float lower = c - radius;
        const float upper = c + radius;
        const float rl = fmaxf(lower, 0.f);
        const float ru = fmaxf(upper, 0.f);

        float lam = (ru - rl) / (upper - lower + EPSV);
        if (lower >= 0.f) lam = 1.f;
        if (upper < 0.f) lam = 0.f;
        if (isnan(lam)) lam = 0.f;
        lam = fminf(fmaxf(lam, 0.f), 1.f);

        const float beta = (rl - lam * lower) * 0.5f;
        const float delta = fabsf(beta);

        out_central[bd] = lam * c + beta;
        out_err[bd] = lam * e;

        // Patch diagonal: local diag row tid has its element at global col dg.
        // Ordered after the zero-fill by the __syncthreads above.
        ((float*)diag_blk)[(size_t)tid * D + dg] = delta;

        ((float*)&s_lam[dc4])[lane] = lam;
    }
    __syncthreads();

    // Pass 2: scale register-resident values and store scaled_pd.
    // new_pd layout: (B, N+D, D); rows [0, N) are scaled_pd.
    const float4 lam4 = s_lam[d4];
    float4* o = out_pd4 + (size_t)b * PB4 + (size_t)(g * NCHUNK) * D4
                + h * DC4 + d4;
#pragma unroll
    for (int n = 0; n < NCHUNK; n++) {
        float4 w;
        w.x = v[n].x * lam4.x;
        w.y = v[n].y * lam4.y;
        w.z = v[n].z * lam4.z;
        w.w = v[n].w * lam4.w;
        o[(size_t)n * D4] = w;
    }
}

extern "C" void kernel_launch(void* const* d_in, const int* in_sizes, int n_in,
                              void* d_out, int out_size) {
    const float* cv = (const float*)d_in[0];   // (256, 512)
    const float* pd = (const float*)d_in[1];   // (256, 256, 512)
    const float* err = (const float*)d_in[2];  // (256, 512)

    float* out = (float*)d_out;
    // Output layout: [new_central (B*D)] [new_pd (B*(N+D)*D)] [new_err (B*D)]
    float* out_central = out;
    float* out_pd = out + (size_t)B * D;
    float* out_err = out + (size_t)B * D + (size_t)B * (N + D) * D;

    dim3 grid(B, DSPLIT);  // 4096 blocks
    k_mega<<<grid, 256>>>(cv, (const float4*)pd, err,
                          out_central, (float4*)out_pd, out_err);
}